// round 1
// baseline (speedup 1.0000x reference)
#include <cuda_runtime.h>

// channel_attention collapses to: out = LN_c(Wp @ x + bp)*gp + betap + x
// (softmax row-sum == 1 makes the whole q/k/attention branch an identity).
//
// Shapes: x [BO=1024][C=128][S=400] fp32, row-major, S contiguous.
// Per block: one (b,o) and an 80-wide s tile. GEMM M=C=128, N=80, K=128 in
// fp32 using packed fma.rn.f32x2, then warp-local LayerNorm epilogue.

#define C        128
#define S        400
#define TS       80
#define NTILE    (S / TS)        // 5
#define THREADS  256
#define WT_PITCH 132             // 128 + 4 pad (keeps 16B row alignment)
#define XS_PITCH 84              // 80 + 4 pad  (keeps 16B row alignment)

__device__ __forceinline__ unsigned long long pk2(float lo, float hi) {
    unsigned long long r;
    asm("mov.b64 %0, {%1,%2};" : "=l"(r) : "f"(lo), "f"(hi));
    return r;
}
__device__ __forceinline__ void fma2(unsigned long long& d,
                                     unsigned long long a,
                                     unsigned long long b) {
    asm("fma.rn.f32x2 %0, %1, %2, %0;" : "+l"(d) : "l"(a), "l"(b));
}
__device__ __forceinline__ float2 up2(unsigned long long v) {
    float2 r;
    asm("mov.b64 {%0,%1}, %2;" : "=f"(r.x), "=f"(r.y) : "l"(v));
    return r;
}

extern __shared__ float s_mem[];

__global__ __launch_bounds__(THREADS, 1)
void ca_kernel(const float* __restrict__ x,
               const float* __restrict__ Wp,
               const float* __restrict__ bp,
               const float* __restrict__ gp,
               const float* __restrict__ betap,
               float* __restrict__ out) {
    float* Wt    = s_mem;                    // [128][WT_PITCH]  Wt[k][j] = Wp[j][k]
    float* Xs    = Wt + C * WT_PITCH;        // [128][XS_PITCH]  Xs[c][s_local]
    float* s_bp  = Xs + C * XS_PITCH;        // [128]
    float* s_gp  = s_bp + C;                 // [128]
    float* s_bt  = s_gp + C;                 // [128]

    const int tid  = threadIdx.x;
    const int bo   = blockIdx.x / NTILE;
    const int tile = blockIdx.x % NTILE;
    const float* xb = x   + (size_t)bo * C * S + tile * TS;
    float*       ob = out + (size_t)bo * C * S + tile * TS;

    // ---- fill smem ----
    // Wp transposed (coalesced global read; one-time smem write conflicts OK)
    #pragma unroll 8
    for (int idx = tid; idx < C * C; idx += THREADS) {
        int j = idx >> 7;
        int k = idx & 127;
        Wt[k * WT_PITCH + j] = Wp[idx];
    }
    if (tid < C) {
        s_bp[tid] = bp[tid];
        s_gp[tid] = gp[tid];
        s_bt[tid] = betap[tid];
    }
    // X tile: 128 rows x 80 floats, vectorized
    #pragma unroll 10
    for (int t = tid; t < C * (TS / 4); t += THREADS) {
        int c = t / (TS / 4);
        int q = t % (TS / 4);
        float4 v = *(const float4*)(xb + (size_t)c * S + q * 4);
        *(float4*)(Xs + c * XS_PITCH + q * 4) = v;
    }
    __syncthreads();

    // ---- register-tiled GEMM: thread (tj, ts) computes j = tj*4..+3, s = ts*10..+9
    const int tj = tid & 31;      // lane  -> 4-row j group (warp covers all 128 j)
    const int ts = tid >> 5;      // warp  -> 10-col s group
    const int sb = ts * 10;

    unsigned long long acc[4][5];
    #pragma unroll
    for (int m = 0; m < 4; m++)
        #pragma unroll
        for (int n = 0; n < 5; n++) acc[m][n] = 0ull;

    const float* wbase = Wt + tj * 4;
    const float* xbase = Xs + sb;

    #pragma unroll 2
    for (int k = 0; k < C; k++) {
        float4 a = *(const float4*)(wbase + k * WT_PITCH);
        unsigned long long A0 = pk2(a.x, a.x);
        unsigned long long A1 = pk2(a.y, a.y);
        unsigned long long A2 = pk2(a.z, a.z);
        unsigned long long A3 = pk2(a.w, a.w);
        const unsigned long long* bp2 =
            (const unsigned long long*)(xbase + k * XS_PITCH);
        unsigned long long b0 = bp2[0], b1 = bp2[1], b2 = bp2[2],
                           b3 = bp2[3], b4 = bp2[4];

        fma2(acc[0][0], A0, b0); fma2(acc[0][1], A0, b1); fma2(acc[0][2], A0, b2);
        fma2(acc[0][3], A0, b3); fma2(acc[0][4], A0, b4);
        fma2(acc[1][0], A1, b0); fma2(acc[1][1], A1, b1); fma2(acc[1][2], A1, b2);
        fma2(acc[1][3], A1, b3); fma2(acc[1][4], A1, b4);
        fma2(acc[2][0], A2, b0); fma2(acc[2][1], A2, b1); fma2(acc[2][2], A2, b2);
        fma2(acc[2][3], A2, b3); fma2(acc[2][4], A2, b4);
        fma2(acc[3][0], A3, b0); fma2(acc[3][1], A3, b1); fma2(acc[3][2], A3, b2);
        fma2(acc[3][3], A3, b3); fma2(acc[3][4], A3, b4);
    }

    // ---- epilogue: add bp, LayerNorm over j (intra-warp), affine, residual ----
    float y[4][10];
    #pragma unroll
    for (int m = 0; m < 4; m++) {
        float bj = s_bp[tj * 4 + m];
        #pragma unroll
        for (int n = 0; n < 5; n++) {
            float2 v = up2(acc[m][n]);
            y[m][2 * n]     = v.x + bj;
            y[m][2 * n + 1] = v.y + bj;
        }
    }

    float mu[10], rs[10];
    #pragma unroll
    for (int col = 0; col < 10; col++) {
        float sv = 0.f, sq = 0.f;
        #pragma unroll
        for (int m = 0; m < 4; m++) {
            float v = y[m][col];
            sv += v;
            sq = fmaf(v, v, sq);
        }
        #pragma unroll
        for (int off = 16; off > 0; off >>= 1) {
            sv += __shfl_xor_sync(0xffffffffu, sv, off);
            sq += __shfl_xor_sync(0xffffffffu, sq, off);
        }
        float m_  = sv * (1.0f / 128.0f);
        float var = sq * (1.0f / 128.0f) - m_ * m_;
        mu[col] = m_;
        rs[col] = rsqrtf(var + 1e-5f);
    }

    #pragma unroll
    for (int m = 0; m < 4; m++) {
        int j = tj * 4 + m;
        float g = s_gp[j];
        float b = s_bt[j];
        const float* xrow = Xs + j * XS_PITCH + sb;
        float* orow = ob + (size_t)j * S + sb;
        #pragma unroll
        for (int n = 0; n < 5; n++) {
            float2 o;
            o.x = (y[m][2 * n]     - mu[2 * n])     * rs[2 * n]     * g + b + xrow[2 * n];
            o.y = (y[m][2 * n + 1] - mu[2 * n + 1]) * rs[2 * n + 1] * g + b + xrow[2 * n + 1];
            *(float2*)(orow + 2 * n) = o;
        }
    }
}

extern "C" void kernel_launch(void* const* d_in, const int* in_sizes, int n_in,
                              void* d_out, int out_size) {
    // metadata order: x, Wq, bq, gq, betaq, Wk, bk, gk, betak, Wp, bp, gp, betap
    const float* x     = (const float*)d_in[0];
    const float* Wp    = (const float*)d_in[9];
    const float* bp    = (const float*)d_in[10];
    const float* gp    = (const float*)d_in[11];
    const float* betap = (const float*)d_in[12];
    float* out = (float*)d_out;

    const int BO = in_sizes[0] / (C * S);   // 1024
    const size_t smem =
        (size_t)(C * WT_PITCH + C * XS_PITCH + 3 * C) * sizeof(float);

    cudaFuncSetAttribute(ca_kernel,
                         cudaFuncAttributeMaxDynamicSharedMemorySize,
                         (int)smem);
    ca_kernel<<<BO * NTILE, THREADS, smem>>>(x, Wp, bp, gp, betap, out);
}